// round 1
// baseline (speedup 1.0000x reference)
#include <cuda_runtime.h>

// Problem constants
#define Hh   16
#define Ss   1024
#define Dd   1024
#define HDd  64
#define Bb   8
#define BHh  (Bb*Hh)      // 128
#define Mtot (Bb*Ss)      // 8192

// Scratch: Q/K/V in head-major layout [B*H][S][HD]  (~33.5 MB each)
__device__ float g_Q[(size_t)BHh*Ss*HDd];
__device__ float g_K[(size_t)BHh*Ss*HDd];
__device__ float g_V[(size_t)BHh*Ss*HDd];

// ---------------------------------------------------------------------------
// Projection GEMM: Out = X @ W  for W in {Wq,Wk,Wv} (blockIdx.z selects)
// X: [8192,1024] row-major, W: [1024,1024] row-major.
// Output written directly in head-major [B*H][S][HD].
// Tile: 128x128, K-step 8, 256 threads, 8x8 per-thread microtile.
// ---------------------------------------------------------------------------
__global__ __launch_bounds__(256) void proj_kernel(
    const float* __restrict__ X,
    const float* __restrict__ Wq,
    const float* __restrict__ Wk,
    const float* __restrict__ Wv)
{
    const float* W   = (blockIdx.z == 0) ? Wq : (blockIdx.z == 1 ? Wk : Wv);
    float*       Out = (blockIdx.z == 0) ? g_Q : (blockIdx.z == 1 ? g_K : g_V);

    __shared__ float As[8][128];   // [k][m]
    __shared__ float Bs[8][128];   // [k][n]

    const int tid = threadIdx.x;
    const int m0 = blockIdx.y * 128;
    const int n0 = blockIdx.x * 128;

    const int ty = tid >> 4, tx = tid & 15;
    const int mi = ty * 8,  ni = tx * 8;

    // load assignments
    const int arow = tid >> 1;            // 0..127
    const int aseg = (tid & 1) * 4;       // 0 or 4
    const int brow = tid >> 5;            // 0..7
    const int bcol = (tid & 31) * 4;      // 0..124

    float acc[8][8];
    #pragma unroll
    for (int i = 0; i < 8; i++)
        #pragma unroll
        for (int j = 0; j < 8; j++) acc[i][j] = 0.f;

    for (int k0 = 0; k0 < Dd; k0 += 8) {
        float4 av = *(const float4*)(X + (size_t)(m0 + arow) * Dd + k0 + aseg);
        float4 bv = *(const float4*)(W + (size_t)(k0 + brow) * Dd + n0 + bcol);
        __syncthreads();   // previous iteration's compute done
        As[aseg + 0][arow] = av.x;
        As[aseg + 1][arow] = av.y;
        As[aseg + 2][arow] = av.z;
        As[aseg + 3][arow] = av.w;
        *(float4*)&Bs[brow][bcol] = bv;
        __syncthreads();

        #pragma unroll
        for (int k = 0; k < 8; k++) {
            float a[8], bb[8];
            *(float4*)(a)      = *(const float4*)&As[k][mi];
            *(float4*)(a + 4)  = *(const float4*)&As[k][mi + 4];
            *(float4*)(bb)     = *(const float4*)&Bs[k][ni];
            *(float4*)(bb + 4) = *(const float4*)&Bs[k][ni + 4];
            #pragma unroll
            for (int i = 0; i < 8; i++)
                #pragma unroll
                for (int j = 0; j < 8; j++)
                    acc[i][j] += a[i] * bb[j];
        }
    }

    // Write out in head-major layout
    #pragma unroll
    for (int i = 0; i < 8; i++) {
        int m = m0 + mi + i;
        int bidx = m >> 10;        // /1024
        int s    = m & 1023;
        #pragma unroll
        for (int j = 0; j < 8; j += 4) {
            int n = n0 + ni + j;
            int h = n >> 6;        // /64
            int d = n & 63;
            float4 o = make_float4(acc[i][j], acc[i][j + 1], acc[i][j + 2], acc[i][j + 3]);
            *(float4*)(Out + ((size_t)(bidx * Hh + h) * Ss + s) * HDd + d) = o;
        }
    }
}

// ---------------------------------------------------------------------------
// Attention: one CTA per (b,h, 64-row q-block). Streams K/V in 64-row tiles.
// Unsafe softmax: e = exp(qk/8)*mask;  out = (e@V) / (rowsum(e)+1e-8)
// Smem: Qs,Ks transposed [d][row] for conflict-free float4 reads;
//       Vs natural [t][n]; Ps natural [i][j].
// ---------------------------------------------------------------------------
__global__ __launch_bounds__(256) void attn_kernel(
    const float* __restrict__ mask, float* __restrict__ out)
{
    const int LD = 68;   // padded row stride (floats)
    extern __shared__ float sm[];
    float* Qs = sm;                 // [64][68]  [d][i]
    float* Ks = sm + 64 * LD;       // [64][68]  [d][j]
    float* Vs = sm + 2 * 64 * LD;   // [64][68]  [t][n]
    float* Ps = sm + 3 * 64 * LD;   // [64][68]  [i][j]

    const int tid = threadIdx.x;
    const int bh = blockIdx.y;
    const int b = bh >> 4;
    const int h = bh & 15;
    const int q0 = blockIdx.x * 64;

    const float* Qg = g_Q + (size_t)bh * Ss * HDd;
    const float* Kg = g_K + (size_t)bh * Ss * HDd;
    const float* Vg = g_V + (size_t)bh * Ss * HDd;
    const float* mb = mask + (size_t)b * Ss * Ss;

    const int lrow = tid >> 2;            // 0..63
    const int lseg = (tid & 3) * 16;      // 0,16,32,48

    // load Q tile transposed
    {
        const float4* src = (const float4*)(Qg + (size_t)(q0 + lrow) * HDd + lseg);
        #pragma unroll
        for (int c = 0; c < 4; c++) {
            float4 v = src[c];
            int d = lseg + c * 4;
            Qs[(d + 0) * LD + lrow] = v.x;
            Qs[(d + 1) * LD + lrow] = v.y;
            Qs[(d + 2) * LD + lrow] = v.z;
            Qs[(d + 3) * LD + lrow] = v.w;
        }
    }

    const int ty = tid >> 4, tx = tid & 15;
    const int i0 = ty * 4, j0 = tx * 4;

    float acc[4][4];
    #pragma unroll
    for (int i = 0; i < 4; i++)
        #pragma unroll
        for (int j = 0; j < 4; j++) acc[i][j] = 0.f;
    float rsum[4] = {0.f, 0.f, 0.f, 0.f};

    __syncthreads();

    for (int t0 = 0; t0 < Ss; t0 += 64) {
        // load K tile (transposed) + V tile (natural)
        {
            const float4* ksrc = (const float4*)(Kg + (size_t)(t0 + lrow) * HDd + lseg);
            const float4* vsrc = (const float4*)(Vg + (size_t)(t0 + lrow) * HDd + lseg);
            #pragma unroll
            for (int c = 0; c < 4; c++) {
                float4 kv = ksrc[c];
                int d = lseg + c * 4;
                Ks[(d + 0) * LD + lrow] = kv.x;
                Ks[(d + 1) * LD + lrow] = kv.y;
                Ks[(d + 2) * LD + lrow] = kv.z;
                Ks[(d + 3) * LD + lrow] = kv.w;
                float4 vv = vsrc[c];
                *(float4*)&Vs[lrow * LD + d] = vv;
            }
        }
        __syncthreads();

        // scores: sc[i][j] = sum_d Q[i][d]*K[j][d]
        float sc[4][4];
        #pragma unroll
        for (int i = 0; i < 4; i++)
            #pragma unroll
            for (int j = 0; j < 4; j++) sc[i][j] = 0.f;

        #pragma unroll
        for (int d = 0; d < 64; d++) {
            float q[4], k[4];
            *(float4*)q = *(const float4*)&Qs[d * LD + i0];
            *(float4*)k = *(const float4*)&Ks[d * LD + j0];
            #pragma unroll
            for (int ii = 0; ii < 4; ii++)
                #pragma unroll
                for (int jj = 0; jj < 4; jj++)
                    sc[ii][jj] += q[ii] * k[jj];
        }

        // exp * mask, write P, row-sum reduce over tx lanes
        #pragma unroll
        for (int ii = 0; ii < 4; ii++) {
            float4 mv = *(const float4*)(mb + (size_t)(q0 + i0 + ii) * Ss + t0 + j0);
            float m[4];
            *(float4*)m = mv;
            float e[4];
            float rp = 0.f;
            #pragma unroll
            for (int jj = 0; jj < 4; jj++) {
                e[jj] = __expf(sc[ii][jj] * 0.125f) * m[jj];
                rp += e[jj];
            }
            *(float4*)&Ps[(i0 + ii) * LD + j0] = *(float4*)e;
            rp += __shfl_xor_sync(0xffffffffu, rp, 1);
            rp += __shfl_xor_sync(0xffffffffu, rp, 2);
            rp += __shfl_xor_sync(0xffffffffu, rp, 4);
            rp += __shfl_xor_sync(0xffffffffu, rp, 8);
            rsum[ii] += rp;
        }
        __syncthreads();

        // PV: acc[i][n] += P[i][k2] * V[k2][n]
        #pragma unroll
        for (int k2 = 0; k2 < 64; k2 += 4) {
            float p[4][4];
            #pragma unroll
            for (int ii = 0; ii < 4; ii++)
                *(float4*)p[ii] = *(const float4*)&Ps[(i0 + ii) * LD + k2];
            #pragma unroll
            for (int kk = 0; kk < 4; kk++) {
                float v[4];
                *(float4*)v = *(const float4*)&Vs[(k2 + kk) * LD + j0];
                #pragma unroll
                for (int ii = 0; ii < 4; ii++)
                    #pragma unroll
                    for (int jj = 0; jj < 4; jj++)
                        acc[ii][jj] += p[ii][kk] * v[jj];
            }
        }
        __syncthreads();
    }

    // final: divide by rowsum + 1e-8, write [B,S,D]
    #pragma unroll
    for (int ii = 0; ii < 4; ii++) {
        float inv = 1.0f / (rsum[ii] + 1e-8f);
        float4 o;
        o.x = acc[ii][0] * inv;
        o.y = acc[ii][1] * inv;
        o.z = acc[ii][2] * inv;
        o.w = acc[ii][3] * inv;
        *(float4*)(out + (size_t)(b * Ss + q0 + i0 + ii) * Dd + h * HDd + j0) = o;
    }
}

// ---------------------------------------------------------------------------
extern "C" void kernel_launch(void* const* d_in, const int* in_sizes, int n_in,
                              void* d_out, int out_size)
{
    const float* x    = (const float*)d_in[0];
    const float* mask = (const float*)d_in[1];
    const float* Wq   = (const float*)d_in[2];
    const float* Wk   = (const float*)d_in[3];
    const float* Wv   = (const float*)d_in[4];
    float* out = (float*)d_out;

    // Projections: Q,K,V in one launch (grid.z selects weight/output)
    dim3 pgrid(Dd / 128, Mtot / 128, 3);
    proj_kernel<<<pgrid, 256>>>(x, Wq, Wk, Wv);

    // Attention
    const int smem_bytes = 4 * 64 * 68 * (int)sizeof(float);  // 69632
    cudaFuncSetAttribute(attn_kernel, cudaFuncAttributeMaxDynamicSharedMemorySize,
                         smem_bytes);
    dim3 agrid(Ss / 64, BHh);
    attn_kernel<<<agrid, 256, smem_bytes>>>(mask, out);
}

// round 3
// speedup vs baseline: 2.2422x; 2.2422x over previous
#include <cuda_runtime.h>
#include <cstdint>

// Problem constants
#define Hh   16
#define Ss   1024
#define Dd   1024
#define HDd  64
#define Bb   8
#define BHh  (Bb*Hh)      // 128
#define Mtot (Bb*Ss)      // 8192

// Scratch: Q/K/V head-major [B*H][S][HD]
__device__ float g_Q[(size_t)BHh*Ss*HDd];
__device__ float g_K[(size_t)BHh*Ss*HDd];
__device__ float g_V[(size_t)BHh*Ss*HDd];

__device__ __forceinline__ uint32_t f2tf32(float x) {
    uint32_t r;
    asm("cvt.rna.tf32.f32 %0, %1;" : "=r"(r) : "f"(x));
    return r;
}

// m16n8k8 tf32 mma, accumulate in-place
__device__ __forceinline__ void mma8(float* c, const uint32_t* a, uint32_t b0, uint32_t b1) {
    asm volatile(
        "mma.sync.aligned.m16n8k8.row.col.f32.tf32.tf32.f32 "
        "{%0,%1,%2,%3}, {%4,%5,%6,%7}, {%8,%9}, {%0,%1,%2,%3};"
        : "+f"(c[0]), "+f"(c[1]), "+f"(c[2]), "+f"(c[3])
        : "r"(a[0]), "r"(a[1]), "r"(a[2]), "r"(a[3]), "r"(b0), "r"(b1));
}

// ---------------------------------------------------------------------------
// Projection GEMM (tensor cores): Out_z = X @ W_z, tile 128x128, K-step 32.
// A smem [m=128][kpad=36]  (row-major, frag banks 4g+tig -> conflict-free)
// B smem [k=32][npad=132]  (natural W layout; col-major frag reads direct)
// 8 warps: wm=wid>>1 (4 x 32 rows), wn=wid&1 (2 x 64 cols).
// ---------------------------------------------------------------------------
#define APAD 36
#define BPAD 132
__global__ __launch_bounds__(256, 2) void proj_mma_kernel(
    const float* __restrict__ X,
    const float* __restrict__ Wq,
    const float* __restrict__ Wk,
    const float* __restrict__ Wv)
{
    __shared__ __align__(16) uint32_t As[128][APAD];
    __shared__ __align__(16) uint32_t Bs[32][BPAD];

    const int tid = threadIdx.x;
    const int wid = tid >> 5, lane = tid & 31;
    const int g = lane >> 2, tig = lane & 3;
    const int wm = wid >> 1, wn = wid & 1;

    const int z  = blockIdx.z;
    const int n0 = blockIdx.x * 128;
    const int m0 = blockIdx.y * 128;
    const float* W = (z == 0) ? Wq : (z == 1 ? Wk : Wv);
    float* Out = (z == 0) ? g_Q : (z == 1 ? g_K : g_V);

    float C[2][8][4];
    #pragma unroll
    for (int mf = 0; mf < 2; mf++)
        #pragma unroll
        for (int nf = 0; nf < 8; nf++)
            #pragma unroll
            for (int r = 0; r < 4; r++) C[mf][nf][r] = 0.f;

    // staging index maps
    const int arow = tid >> 1;              // 0..127
    const int akq  = (tid & 1) * 4;         // float4 pairs: 2 per thread (kq, kq+... )
    const int brow = tid >> 5;              // 0..7 (k rows, 4 per thread via +8)
    const int bc4  = (tid & 31);            // 0..31 (n float4)

    for (int k0 = 0; k0 < Dd; k0 += 32) {
        // load to regs (A: 128x32 = 1024 f4, 4/thread; B: 32x128 = 1024 f4, 4/thread)
        float4 av[4], bv[4];
        #pragma unroll
        for (int i = 0; i < 4; i++) {
            int idx = tid + 256 * i;
            int r = idx >> 3, kq = idx & 7;
            av[i] = *(const float4*)(X + (size_t)(m0 + r) * Dd + k0 + kq * 4);
        }
        #pragma unroll
        for (int i = 0; i < 4; i++) {
            bv[i] = *(const float4*)(W + (size_t)(k0 + brow + i * 8) * Dd + n0 + bc4 * 4);
        }
        __syncthreads();
        #pragma unroll
        for (int i = 0; i < 4; i++) {
            int idx = tid + 256 * i;
            int r = idx >> 3, kq = idx & 7;
            uint4 u = make_uint4(f2tf32(av[i].x), f2tf32(av[i].y),
                                 f2tf32(av[i].z), f2tf32(av[i].w));
            *(uint4*)&As[r][kq * 4] = u;
        }
        #pragma unroll
        for (int i = 0; i < 4; i++) {
            uint4 u = make_uint4(f2tf32(bv[i].x), f2tf32(bv[i].y),
                                 f2tf32(bv[i].z), f2tf32(bv[i].w));
            *(uint4*)&Bs[brow + i * 8][bc4 * 4] = u;
        }
        __syncthreads();

        #pragma unroll
        for (int kf = 0; kf < 4; kf++) {
            uint32_t a[2][4];
            #pragma unroll
            for (int mf = 0; mf < 2; mf++) {
                int r = wm * 32 + mf * 16;
                a[mf][0] = As[r + g][kf * 8 + tig];
                a[mf][1] = As[r + 8 + g][kf * 8 + tig];
                a[mf][2] = As[r + g][kf * 8 + tig + 4];
                a[mf][3] = As[r + 8 + g][kf * 8 + tig + 4];
            }
            #pragma unroll
            for (int nf = 0; nf < 8; nf++) {
                int n = wn * 64 + nf * 8;
                uint32_t b0 = Bs[kf * 8 + tig][n + g];
                uint32_t b1 = Bs[kf * 8 + tig + 4][n + g];
                mma8(C[0][nf], a[0], b0, b1);
                mma8(C[1][nf], a[1], b0, b1);
            }
        }
    }

    // epilogue: head-major scatter, st.v2
    const int hbase = (n0 + wn * 64) >> 6;   // constant per warp
    #pragma unroll
    for (int mf = 0; mf < 2; mf++) {
        int m = m0 + wm * 32 + mf * 16 + g;
        int bidx = m >> 10, s = m & 1023;
        float* base = Out + ((size_t)(bidx * Hh + hbase) * Ss + s) * HDd;
        float* base2 = base + 8 * HDd;       // row m+8
        #pragma unroll
        for (int nf = 0; nf < 8; nf++) {
            int d = nf * 8 + 2 * tig;
            *(float2*)(base + d)  = make_float2(C[mf][nf][0], C[mf][nf][1]);
            *(float2*)(base2 + d) = make_float2(C[mf][nf][2], C[mf][nf][3]);
        }
    }
}

// ---------------------------------------------------------------------------
// Attention (tensor cores): CTA = (bh, 64 q-rows), 4 warps x 16 rows.
// Q in A-fragments (registers, whole kernel). K smem natural [t][dpad],
// V smem transposed [d][tpad]. P stays in registers: C-frag -> A-frag via shfl.
// ---------------------------------------------------------------------------
#define KPAD 68
__global__ __launch_bounds__(128) void attn_mma_kernel(
    const float* __restrict__ mask, float* __restrict__ out)
{
    __shared__ __align__(16) uint32_t Ks[64][KPAD];   // [t][d]
    __shared__ __align__(16) uint32_t Vt[64][KPAD];   // [d][t]

    const int tid = threadIdx.x;
    const int w = tid >> 5, lane = tid & 31;
    const int g = lane >> 2, tig = lane & 3;
    const int bh = blockIdx.y, b = bh >> 4, h = bh & 15;
    const int q0 = blockIdx.x * 64;
    const int i0 = w * 16;

    const float* Qg = g_Q + (size_t)bh * Ss * HDd;
    const float* Kg = g_K + (size_t)bh * Ss * HDd;
    const float* Vg = g_V + (size_t)bh * Ss * HDd;

    // Q fragments: rows q0+i0+g / +8+g, cols kf*8+tig / +4
    uint32_t qf[8][4];
    {
        const float* r0 = Qg + (size_t)(q0 + i0 + g) * HDd;
        const float* r1 = Qg + (size_t)(q0 + i0 + 8 + g) * HDd;
        #pragma unroll
        for (int kf = 0; kf < 8; kf++) {
            qf[kf][0] = f2tf32(r0[kf * 8 + tig]);
            qf[kf][1] = f2tf32(r1[kf * 8 + tig]);
            qf[kf][2] = f2tf32(r0[kf * 8 + tig + 4]);
            qf[kf][3] = f2tf32(r1[kf * 8 + tig + 4]);
        }
    }

    float O[8][4];
    #pragma unroll
    for (int nf = 0; nf < 8; nf++)
        #pragma unroll
        for (int r = 0; r < 4; r++) O[nf][r] = 0.f;
    float rs0 = 0.f, rs1 = 0.f;

    const int srow = tid >> 1;             // 0..63
    const int shalf = (tid & 1) * 8;       // float4 group 0..7 / 8..15

    const float* mrow0 = mask + ((size_t)b * Ss + q0 + i0 + g) * Ss;
    const float* mrow1 = mrow0 + 8 * Ss;

    for (int t0 = 0; t0 < Ss; t0 += 64) {
        __syncthreads();
        // stage K natural, V transposed
        {
            const float4* kp = (const float4*)(Kg + (size_t)(t0 + srow) * HDd) + shalf;
            const float4* vp = (const float4*)(Vg + (size_t)(t0 + srow) * HDd) + shalf;
            #pragma unroll
            for (int c = 0; c < 8; c++) {
                float4 kv = kp[c];
                uint4 u = make_uint4(f2tf32(kv.x), f2tf32(kv.y), f2tf32(kv.z), f2tf32(kv.w));
                *(uint4*)&Ks[srow][(shalf + c) * 4] = u;
                float4 vv = vp[c];
                int d = (shalf + c) * 4;
                Vt[d + 0][srow] = f2tf32(vv.x);
                Vt[d + 1][srow] = f2tf32(vv.y);
                Vt[d + 2][srow] = f2tf32(vv.z);
                Vt[d + 3][srow] = f2tf32(vv.w);
            }
        }
        __syncthreads();

        // scores S = Q K^T  (m=i 16, n=j 64, k=d 64)
        float S[8][4];
        #pragma unroll
        for (int nf = 0; nf < 8; nf++)
            #pragma unroll
            for (int r = 0; r < 4; r++) S[nf][r] = 0.f;
        #pragma unroll
        for (int kf = 0; kf < 8; kf++) {
            #pragma unroll
            for (int nf = 0; nf < 8; nf++) {
                uint32_t b0 = Ks[nf * 8 + g][kf * 8 + tig];
                uint32_t b1 = Ks[nf * 8 + g][kf * 8 + tig + 4];
                mma8(S[nf], qf[kf], b0, b1);
            }
        }

        // P = exp(S/8) * mask  (kept in S as tf32 bits)
        #pragma unroll
        for (int nf = 0; nf < 8; nf++) {
            float2 m0v = *(const float2*)(mrow0 + t0 + nf * 8 + 2 * tig);
            float2 m1v = *(const float2*)(mrow1 + t0 + nf * 8 + 2 * tig);
            float e0 = __expf(S[nf][0] * 0.125f) * m0v.x;
            float e1 = __expf(S[nf][1] * 0.125f) * m0v.y;
            float e2 = __expf(S[nf][2] * 0.125f) * m1v.x;
            float e3 = __expf(S[nf][3] * 0.125f) * m1v.y;
            rs0 += e0 + e1;
            rs1 += e2 + e3;
            S[nf][0] = __uint_as_float(f2tf32(e0));
            S[nf][1] = __uint_as_float(f2tf32(e1));
            S[nf][2] = __uint_as_float(f2tf32(e2));
            S[nf][3] = __uint_as_float(f2tf32(e3));
        }

        // O += P V  (m=i 16, n=d 64, k=t 64); P C-frag -> A-frag via shfl
        const int srcA = (g << 2) | (tig >> 1);
        const int srcB = (g << 2) | (((tig >> 1) + 2) & 3);
        const bool odd = (tig & 1);
        #pragma unroll
        for (int kt = 0; kt < 8; kt++) {
            uint32_t p0 = __float_as_uint(S[kt][0]);
            uint32_t p1 = __float_as_uint(S[kt][1]);
            uint32_t p2 = __float_as_uint(S[kt][2]);
            uint32_t p3 = __float_as_uint(S[kt][3]);
            uint32_t tA0 = __shfl_sync(0xffffffffu, p0, srcA);
            uint32_t tA1 = __shfl_sync(0xffffffffu, p1, srcA);
            uint32_t tA2 = __shfl_sync(0xffffffffu, p2, srcA);
            uint32_t tA3 = __shfl_sync(0xffffffffu, p3, srcA);
            uint32_t tB0 = __shfl_sync(0xffffffffu, p0, srcB);
            uint32_t tB1 = __shfl_sync(0xffffffffu, p1, srcB);
            uint32_t tB2 = __shfl_sync(0xffffffffu, p2, srcB);
            uint32_t tB3 = __shfl_sync(0xffffffffu, p3, srcB);
            uint32_t a[4];
            a[0] = odd ? tA1 : tA0;   // (row g,   col tig)
            a[1] = odd ? tA3 : tA2;   // (row g+8, col tig)
            a[2] = odd ? tB1 : tB0;   // (row g,   col tig+4)
            a[3] = odd ? tB3 : tB2;   // (row g+8, col tig+4)
            #pragma unroll
            for (int nf = 0; nf < 8; nf++) {
                uint32_t b0 = Vt[nf * 8 + g][kt * 8 + tig];
                uint32_t b1 = Vt[nf * 8 + g][kt * 8 + tig + 4];
                mma8(O[nf], a, b0, b1);
            }
        }
    }

    // row sums across the 4 lanes of each row group
    rs0 += __shfl_xor_sync(0xffffffffu, rs0, 1);
    rs0 += __shfl_xor_sync(0xffffffffu, rs0, 2);
    rs1 += __shfl_xor_sync(0xffffffffu, rs1, 1);
    rs1 += __shfl_xor_sync(0xffffffffu, rs1, 2);
    const float inv0 = 1.0f / (rs0 + 1e-8f);
    const float inv1 = 1.0f / (rs1 + 1e-8f);

    float* o0 = out + ((size_t)b * Ss + q0 + i0 + g) * Dd + h * HDd;
    float* o1 = o0 + 8 * Dd;
    #pragma unroll
    for (int nf = 0; nf < 8; nf++) {
        int d = nf * 8 + 2 * tig;
        *(float2*)(o0 + d) = make_float2(O[nf][0] * inv0, O[nf][1] * inv0);
        *(float2*)(o1 + d) = make_float2(O[nf][2] * inv1, O[nf][3] * inv1);
    }
}

// ---------------------------------------------------------------------------
extern "C" void kernel_launch(void* const* d_in, const int* in_sizes, int n_in,
                              void* d_out, int out_size)
{
    const float* x    = (const float*)d_in[0];
    const float* mask = (const float*)d_in[1];
    const float* Wq   = (const float*)d_in[2];
    const float* Wk   = (const float*)d_in[3];
    const float* Wv   = (const float*)d_in[4];
    float* out = (float*)d_out;

    dim3 pgrid(Dd / 128, Mtot / 128, 3);     // (8, 64, 3)
    proj_mma_kernel<<<pgrid, 256>>>(x, Wq, Wk, Wv);

    dim3 agrid(Ss / 64, BHh);                 // (16, 128)
    attn_mma_kernel<<<agrid, 128>>>(mask, out);
}

// round 5
// speedup vs baseline: 5.3270x; 2.3758x over previous
#include <cuda_runtime.h>
#include <cuda_fp16.h>
#include <cstdint>

// Problem constants
#define Hh   16
#define Ss   1024
#define Dd   1024
#define HDd  64
#define Bb   8
#define BHh  (Bb*Hh)      // 128
#define Mtot (Bb*Ss)      // 8192

// fp16 scratch (device globals; no allocation allowed)
__device__ __half g_X16[(size_t)Mtot*Dd];          // 16.7 MB
__device__ __half g_W16[(size_t)3*Dd*Dd];          // 6.3 MB
__device__ __half g_Q16[(size_t)BHh*Ss*HDd];       // head-major [bh][s][64]
__device__ __half g_K16[(size_t)BHh*Ss*HDd];
__device__ __half g_V16[(size_t)BHh*Ss*HDd];

// ---------------------------------------------------------------------------
__device__ __forceinline__ uint32_t h2u(__half2 h) {
    union { __half2 h; uint32_t u; } c;
    c.h = h;
    return c.u;
}
__device__ __forceinline__ uint32_t smem_u32(const void* p) {
    uint32_t a;
    asm("{ .reg .u64 t; cvta.to.shared.u64 t, %1; cvt.u32.u64 %0, t; }" : "=r"(a) : "l"(p));
    return a;
}
#define CP_ASYNC(dst, src) \
    asm volatile("cp.async.ca.shared.global [%0], [%1], 16;" :: "r"(dst), "l"(src) : "memory")
#define CP_COMMIT() asm volatile("cp.async.commit_group;" ::: "memory")
#define CP_WAIT(n)  asm volatile("cp.async.wait_group %0;" :: "n"(n) : "memory")

__device__ __forceinline__ void ldsm_x4(uint32_t* r, uint32_t addr) {
    asm volatile("ldmatrix.sync.aligned.m8n8.x4.shared.b16 {%0,%1,%2,%3}, [%4];"
                 : "=r"(r[0]), "=r"(r[1]), "=r"(r[2]), "=r"(r[3]) : "r"(addr));
}
__device__ __forceinline__ void ldsm_x4_t(uint32_t* r, uint32_t addr) {
    asm volatile("ldmatrix.sync.aligned.m8n8.x4.trans.shared.b16 {%0,%1,%2,%3}, [%4];"
                 : "=r"(r[0]), "=r"(r[1]), "=r"(r[2]), "=r"(r[3]) : "r"(addr));
}
// fp16 m16n8k16 mma, fp32 accum in-place
__device__ __forceinline__ void mma16(float* c, const uint32_t* a, uint32_t b0, uint32_t b1) {
    asm volatile(
        "mma.sync.aligned.m16n8k16.row.col.f32.f16.f16.f32 "
        "{%0,%1,%2,%3}, {%4,%5,%6,%7}, {%8,%9}, {%0,%1,%2,%3};"
        : "+f"(c[0]), "+f"(c[1]), "+f"(c[2]), "+f"(c[3])
        : "r"(a[0]), "r"(a[1]), "r"(a[2]), "r"(a[3]), "r"(b0), "r"(b1));
}
// ldmatrix address: lanes 0-15 -> rows r0..r0+15 @ c0b; lanes 16-31 -> same rows @ c0b+16
__device__ __forceinline__ uint32_t ldsm_addr(uint32_t base, int r0, int c0b,
                                              int rowb, int lane) {
    return base + (uint32_t)(r0 + (lane & 15)) * rowb + c0b + ((lane >> 4) << 4);
}

// ---------------------------------------------------------------------------
// fp32 -> fp16 convert (pre-pass)
// ---------------------------------------------------------------------------
__global__ void conv_fp16(const float4* __restrict__ src, __half2* __restrict__ dst, int n4)
{
    int i = blockIdx.x * blockDim.x + threadIdx.x;
    if (i < n4) {
        float4 v = src[i];
        dst[2*i]   = __floats2half2_rn(v.x, v.y);
        dst[2*i+1] = __floats2half2_rn(v.z, v.w);
    }
}

// ---------------------------------------------------------------------------
// Projection GEMM, fp16 HMMA: Out_z = X @ W_z. Tile 128x128, K-step 64, 2-stage cp.async.
// A smem [2][128][72] fp16 (pad 8), B smem [2][64][136] fp16 (pad 8).
// 8 warps: wm=wid&3 (m32 rows), wn=wid>>2 (n64 cols). Outputs head-major fp16.
// ---------------------------------------------------------------------------
#define PA_ROWB 144   // 72 halves
#define PB_ROWB 272   // 136 halves
#define PA_STAGE 18432
#define PB_STAGE 17408
#define PROJ_SMEM (2*PA_STAGE + 2*PB_STAGE)   // 71680

__global__ __launch_bounds__(256, 1) void proj16_kernel()
{
    extern __shared__ char sm[];
    const uint32_t sb = smem_u32(sm);
    const uint32_t Ab = sb, Bb_ = sb + 2*PA_STAGE;

    const int tid = threadIdx.x, wid = tid >> 5, lane = tid & 31;
    const int g = lane >> 2, tig = lane & 3;
    const int wm = wid & 3, wn = wid >> 2;

    const int z  = blockIdx.z;
    const int n0 = blockIdx.x * 128;
    const int m0 = blockIdx.y * 128;
    const __half* Xp = g_X16 + (size_t)m0 * Dd;
    const __half* Wp = g_W16 + (size_t)z * Dd * Dd + n0;
    __half* Out = (z == 0) ? g_Q16 : (z == 1 ? g_K16 : g_V16);

    float C[2][8][4];
    #pragma unroll
    for (int mf = 0; mf < 2; mf++)
        #pragma unroll
        for (int nf = 0; nf < 8; nf++)
            #pragma unroll
            for (int r = 0; r < 4; r++) C[mf][nf][r] = 0.f;

    auto stage = [&](int kt, int buf) {
        const int k0 = kt * 64;
        #pragma unroll
        for (int i = 0; i < 4; i++) {           // A: 1024 16B chunks
            int ci = tid + 256 * i;
            int row = ci >> 3, seg = ci & 7;
            uint32_t d = Ab + buf * PA_STAGE + row * PA_ROWB + seg * 16;
            CP_ASYNC(d, Xp + (size_t)row * Dd + k0 + seg * 8);
        }
        #pragma unroll
        for (int i = 0; i < 4; i++) {           // B: 1024 16B chunks
            int ci = tid + 256 * i;
            int row = ci >> 4, seg = ci & 15;
            uint32_t d = Bb_ + buf * PB_STAGE + row * PB_ROWB + seg * 16;
            CP_ASYNC(d, Wp + (size_t)(k0 + row) * Dd + seg * 8);
        }
        CP_COMMIT();
    };

    stage(0, 0);
    for (int kt = 0; kt < 16; kt++) {
        if (kt < 15) { stage(kt + 1, (kt + 1) & 1); CP_WAIT(1); }
        else         { CP_WAIT(0); }
        __syncthreads();

        const uint32_t ab = Ab + (kt & 1) * PA_STAGE;
        const uint32_t bbuf = Bb_ + (kt & 1) * PB_STAGE;
        #pragma unroll
        for (int k16 = 0; k16 < 4; k16++) {
            uint32_t a[2][4];
            #pragma unroll
            for (int mf = 0; mf < 2; mf++)
                ldsm_x4(a[mf], ldsm_addr(ab, wm * 32 + mf * 16, k16 * 32, PA_ROWB, lane));
            #pragma unroll
            for (int nfp = 0; nfp < 4; nfp++) {
                uint32_t r[4];
                ldsm_x4_t(r, ldsm_addr(bbuf, k16 * 16, (wn * 64 + nfp * 16) * 2, PB_ROWB, lane));
                #pragma unroll
                for (int mf = 0; mf < 2; mf++) {
                    mma16(C[mf][2*nfp],     a[mf], r[0], r[1]);
                    mma16(C[mf][2*nfp + 1], a[mf], r[2], r[3]);
                }
            }
        }
        __syncthreads();
    }

    // epilogue: head-major fp16 scatter
    const int h = (n0 >> 6) + wn;
    #pragma unroll
    for (int mf = 0; mf < 2; mf++) {
        int m = m0 + wm * 32 + mf * 16 + g;
        int bidx = m >> 10, s = m & 1023;
        __half* base  = Out + ((size_t)(bidx * Hh + h) * Ss + s) * HDd;
        __half* base2 = base + 8 * HDd;
        #pragma unroll
        for (int nf = 0; nf < 8; nf++) {
            int d = nf * 8 + 2 * tig;
            *(__half2*)(base + d)  = __floats2half2_rn(C[mf][nf][0], C[mf][nf][1]);
            *(__half2*)(base2 + d) = __floats2half2_rn(C[mf][nf][2], C[mf][nf][3]);
        }
    }
}

// ---------------------------------------------------------------------------
// Attention, fp16 HMMA: CTA = 256 q-rows x (b,h); 8 warps, each m32.
// K/V staged fp16 [64][72] (2-stage cp.async), Q staged once [256][72].
// P: S C-frag -> fp16 A-frag via pack (no shuffle). Unsafe softmax in fp32.
// ---------------------------------------------------------------------------
#define A_ROWB 144                 // 72 halves
#define AQ_BYTES (256*A_ROWB)      // 36864
#define AKV_BYTES (64*A_ROWB)      // 9216
#define ATTN_SMEM (AQ_BYTES + 4*AKV_BYTES)   // 73728

__global__ __launch_bounds__(256, 1) void attn16_kernel(
    const float* __restrict__ mask, float* __restrict__ out)
{
    extern __shared__ char sm[];
    const uint32_t sb = smem_u32(sm);
    const uint32_t Qb = sb, Kb = sb + AQ_BYTES, Vb = Kb + 2*AKV_BYTES;

    const int tid = threadIdx.x, w = tid >> 5, lane = tid & 31;
    const int g = lane >> 2, tig = lane & 3;
    const int bh = blockIdx.y, b = bh >> 4, h = bh & 15;
    const int q0 = blockIdx.x * 256;
    const int i0 = w * 32;

    const __half* Qg = g_Q16 + (size_t)bh * Ss * HDd + (size_t)q0 * HDd;
    const __half* Kg = g_K16 + (size_t)bh * Ss * HDd;
    const __half* Vg = g_V16 + (size_t)bh * Ss * HDd;

    auto stageKV = [&](int t0, int buf) {
        #pragma unroll
        for (int i = 0; i < 2; i++) {          // K: 512 chunks / 256 thr
            int ci = tid + 256 * i;
            int row = ci >> 3, seg = ci & 7;
            CP_ASYNC(Kb + buf * AKV_BYTES + row * A_ROWB + seg * 16,
                     Kg + (size_t)(t0 + row) * HDd + seg * 8);
        }
        #pragma unroll
        for (int i = 0; i < 2; i++) {          // V
            int ci = tid + 256 * i;
            int row = ci >> 3, seg = ci & 7;
            CP_ASYNC(Vb + buf * AKV_BYTES + row * A_ROWB + seg * 16,
                     Vg + (size_t)(t0 + row) * HDd + seg * 8);
        }
        CP_COMMIT();
    };

    // prologue: Q (2048 chunks) + KV tile 0
    #pragma unroll
    for (int i = 0; i < 8; i++) {
        int ci = tid + 256 * i;
        int row = ci >> 3, seg = ci & 7;
        CP_ASYNC(Qb + row * A_ROWB + seg * 16, Qg + (size_t)row * HDd + seg * 8);
    }
    stageKV(0, 0);
    CP_WAIT(0);
    __syncthreads();

    uint32_t qf[2][4][4];
    #pragma unroll
    for (int mf = 0; mf < 2; mf++)
        #pragma unroll
        for (int k16 = 0; k16 < 4; k16++)
            ldsm_x4(qf[mf][k16], ldsm_addr(Qb, i0 + mf * 16, k16 * 32, A_ROWB, lane));

    float O[2][8][4];
    #pragma unroll
    for (int mf = 0; mf < 2; mf++)
        #pragma unroll
        for (int nf = 0; nf < 8; nf++)
            #pragma unroll
            for (int r = 0; r < 4; r++) O[mf][nf][r] = 0.f;
    float rs[2][2] = {{0.f, 0.f}, {0.f, 0.f}};

    const float* mbase = mask + ((size_t)b * Ss + q0 + i0) * Ss;

    for (int t = 0; t < 16; t++) {
        const int t0 = t * 64, buf = t & 1;
        if (t < 15) { stageKV(t0 + 64, buf ^ 1); CP_WAIT(1); }
        else        { CP_WAIT(0); }
        __syncthreads();

        // S = Q K^T
        float S[2][8][4];
        #pragma unroll
        for (int mf = 0; mf < 2; mf++)
            #pragma unroll
            for (int nf = 0; nf < 8; nf++)
                #pragma unroll
                for (int r = 0; r < 4; r++) S[mf][nf][r] = 0.f;
        const uint32_t kb = Kb + buf * AKV_BYTES;
        #pragma unroll
        for (int k16 = 0; k16 < 4; k16++) {
            #pragma unroll
            for (int nfp = 0; nfp < 4; nfp++) {
                uint32_t r[4];
                ldsm_x4(r, ldsm_addr(kb, nfp * 16, k16 * 32, A_ROWB, lane));
                #pragma unroll
                for (int mf = 0; mf < 2; mf++) {
                    mma16(S[mf][2*nfp],     qf[mf][k16], r[0], r[2]);
                    mma16(S[mf][2*nfp + 1], qf[mf][k16], r[1], r[3]);
                }
            }
        }

        // P = exp(S/8) * mask, packed fp16
        uint32_t Pp[2][8][2];
        #pragma unroll
        for (int mf = 0; mf < 2; mf++) {
            #pragma unroll
            for (int nf = 0; nf < 8; nf++) {
                const float* mr = mbase + (size_t)(mf * 16 + g) * Ss + t0 + nf * 8 + 2 * tig;
                float2 m01 = *(const float2*)mr;
                float2 m23 = *(const float2*)(mr + 8 * Ss);
                float e0 = __expf(S[mf][nf][0] * 0.125f) * m01.x;
                float e1 = __expf(S[mf][nf][1] * 0.125f) * m01.y;
                float e2 = __expf(S[mf][nf][2] * 0.125f) * m23.x;
                float e3 = __expf(S[mf][nf][3] * 0.125f) * m23.y;
                rs[mf][0] += e0 + e1;
                rs[mf][1] += e2 + e3;
                Pp[mf][nf][0] = h2u(__floats2half2_rn(e0, e1));
                Pp[mf][nf][1] = h2u(__floats2half2_rn(e2, e3));
            }
        }

        // O += P V
        const uint32_t vb = Vb + buf * AKV_BYTES;
        #pragma unroll
        for (int kt = 0; kt < 4; kt++) {
            #pragma unroll
            for (int nfp = 0; nfp < 4; nfp++) {
                uint32_t r[4];
                ldsm_x4_t(r, ldsm_addr(vb, kt * 16, nfp * 32, A_ROWB, lane));
                #pragma unroll
                for (int mf = 0; mf < 2; mf++) {
                    uint32_t a[4] = { Pp[mf][2*kt][0], Pp[mf][2*kt][1],
                                      Pp[mf][2*kt + 1][0], Pp[mf][2*kt + 1][1] };
                    mma16(O[mf][2*nfp],     a, r[0], r[1]);
                    mma16(O[mf][2*nfp + 1], a, r[2], r[3]);
                }
            }
        }
        __syncthreads();
    }

    // normalize + store
    #pragma unroll
    for (int mf = 0; mf < 2; mf++) {
        float r0 = rs[mf][0], r1 = rs[mf][1];
        r0 += __shfl_xor_sync(0xffffffffu, r0, 1);
        r0 += __shfl_xor_sync(0xffffffffu, r0, 2);
        r1 += __shfl_xor_sync(0xffffffffu, r1, 1);
        r1 += __shfl_xor_sync(0xffffffffu, r1, 2);
        const float inv0 = 1.0f / (r0 + 1e-8f);
        const float inv1 = 1.0f / (r1 + 1e-8f);
        float* o0 = out + ((size_t)b * Ss + q0 + i0 + mf * 16 + g) * Dd + h * HDd;
        float* o1 = o0 + 8 * Dd;
        #pragma unroll
        for (int nf = 0; nf < 8; nf++) {
            int d = nf * 8 + 2 * tig;
            *(float2*)(o0 + d) = make_float2(O[mf][nf][0] * inv0, O[mf][nf][1] * inv0);
            *(float2*)(o1 + d) = make_float2(O[mf][nf][2] * inv1, O[mf][nf][3] * inv1);
        }
    }
}

// ---------------------------------------------------------------------------
extern "C" void kernel_launch(void* const* d_in, const int* in_sizes, int n_in,
                              void* d_out, int out_size)
{
    const float* x    = (const float*)d_in[0];
    const float* mask = (const float*)d_in[1];
    const float* Wq   = (const float*)d_in[2];
    const float* Wk   = (const float*)d_in[3];
    const float* Wv   = (const float*)d_in[4];
    float* out = (float*)d_out;

    __half* gX; cudaGetSymbolAddress((void**)&gX, g_X16);
    __half* gW; cudaGetSymbolAddress((void**)&gW, g_W16);

    // 1) fp32 -> fp16 pre-pass
    const int n4x = Mtot * Dd / 4;          // 2,097,152
    const int n4w = Dd * Dd / 4;            // 262,144
    conv_fp16<<<(n4x + 255) / 256, 256>>>((const float4*)x, (__half2*)gX, n4x);
    conv_fp16<<<(n4w + 255) / 256, 256>>>((const float4*)Wq, (__half2*)gW, n4w);
    conv_fp16<<<(n4w + 255) / 256, 256>>>((const float4*)Wk, (__half2*)(gW + (size_t)Dd*Dd), n4w);
    conv_fp16<<<(n4w + 255) / 256, 256>>>((const float4*)Wv, (__half2*)(gW + (size_t)2*Dd*Dd), n4w);

    // 2) projections (fp16 HMMA)
    cudaFuncSetAttribute(proj16_kernel, cudaFuncAttributeMaxDynamicSharedMemorySize,
                         PROJ_SMEM);
    dim3 pgrid(Dd / 128, Mtot / 128, 3);    // (8, 64, 3)
    proj16_kernel<<<pgrid, 256, PROJ_SMEM>>>();

    // 3) attention (fp16 HMMA)
    cudaFuncSetAttribute(attn16_kernel, cudaFuncAttributeMaxDynamicSharedMemorySize,
                         ATTN_SMEM);
    dim3 agrid(Ss / 256, BHh);              // (4, 128)
    attn16_kernel<<<agrid, 256, ATTN_SMEM>>>(mask, out);
}